// round 3
// baseline (speedup 1.0000x reference)
#include <cuda_runtime.h>

#define T_STEPS 65536
#define CHUNK   32
#define WARMUP  128
#define NS      2                            // interleaved streams per lane-group
#define NCHUNK  (T_STEPS / CHUNK)            // 2048 chunks
#define GROUPS_PER_WARP 8
#define NWARPS  (NCHUNK / (GROUPS_PER_WARP * NS))  // 128 single-warp blocks

// Scratch for precomputed per-step constants: c1[4], c2[4] per t (+1 row pad for prefetch)
__device__ float g_c12[(T_STEPS + 1) * 8];

__device__ __forceinline__ float fsigm(float x) { return __fdividef(1.f, 1.f + __expf(-x)); }
__device__ __forceinline__ float fsilu(float x) { return __fdividef(x, 1.f + __expf(-x)); }
__device__ __forceinline__ float ftanhf_(float x) { return __fdividef(2.f, 1.f + __expf(-2.f * x)) - 1.f; }

#define SHFL4(v, r) __shfl_sync(0xffffffffu, (v), (r), 4)

// ---------------------------------------------------------------------------
// Parallel precompute: a_t = relu(W1 x_t + b1);
//   c1_t = cv1_b + cv1_w[:,4:28] @ a_t   (the zeros4 block multiplies cols 0:4)
//   c2_t = cv2_b + cv2_w[:,4:28] @ a_t
// ---------------------------------------------------------------------------
__global__ void precompute_kernel(const float* __restrict__ x,
                                  const float* __restrict__ W1, const float* __restrict__ b1,
                                  const float* __restrict__ cv1w, const float* __restrict__ cv1b,
                                  const float* __restrict__ cv2w, const float* __restrict__ cv2b) {
    int t = blockIdx.x * blockDim.x + threadIdx.x;
    if (t >= T_STEPS) return;
    float x0 = x[2 * t], x1 = x[2 * t + 1];
    float a[24];
#pragma unroll
    for (int j = 0; j < 24; ++j) {
        float v = fmaf(W1[2 * j], x0, fmaf(W1[2 * j + 1], x1, b1[j]));
        a[j] = fmaxf(v, 0.f);
    }
#pragma unroll
    for (int i = 0; i < 4; ++i) {
        float c1 = cv1b[i], c2 = cv2b[i];
#pragma unroll
        for (int j = 0; j < 24; ++j) {
            c1 = fmaf(cv1w[i * 32 + 4 + j], a[j], c1);
            c2 = fmaf(cv2w[i * 32 + 4 + j], a[j], c2);
        }
        g_c12[t * 8 + i]     = c1;
        g_c12[t * 8 + 4 + i] = c2;
    }
}

// 4-term dot with split chains
__device__ __forceinline__ float dot4(const float* w, float v0, float v1, float v2, float v3, float c) {
    float a = fmaf(w[0], v0, c);
    a = fmaf(w[1], v1, a);
    float b = w[2] * v2;
    b = fmaf(w[3], v3, b);
    return a + b;
}

// ---------------------------------------------------------------------------
// Sequential scan: 4 lanes cooperate per chunk (lane l owns row l of every
// 4-row matrix), NS independent chunk-streams interleaved per group to hide
// the SHFL/activation latency chain, 8 groups per warp.
// ---------------------------------------------------------------------------
__global__ void __launch_bounds__(32, 1)
scan_kernel(const float* __restrict__ cv1w, const float* __restrict__ cv2w,
            const float* __restrict__ cv3w, const float* __restrict__ cv3b,
            const float* __restrict__ cv4w, const float* __restrict__ cv4b,
            const float* __restrict__ cv5w, const float* __restrict__ cv5b,
            const float* __restrict__ cv6w, const float* __restrict__ cv6b,
            const float* __restrict__ cv7w, const float* __restrict__ cv7b,
            const float* __restrict__ Wih,  const float* __restrict__ bih,
            const float* __restrict__ bhh,
            const float* __restrict__ W3,   const float* __restrict__ b3,
            const float* __restrict__ W4,   const float* __restrict__ b4,
            const float* __restrict__ W5,   const float* __restrict__ b5,
            float* __restrict__ out) {
    const int l    = threadIdx.x & 3;                       // lane within group
    const int grp0 = ((blockIdx.x * 32 + threadIdx.x) >> 2) * NS;  // first chunk of this group

    int pay_lo[NS], start[NS];
#pragma unroll
    for (int s = 0; s < NS; ++s) {
        pay_lo[s] = (grp0 + s) * CHUNK;
        int st = pay_lo[s] - WARMUP;
        start[s] = st < 0 ? 0 : st;   // early chunks: exact from t=0 (true init P=0)
    }

    // ---- per-lane weight rows (registers, shared by both streams) ----
    float M1[4], M2[4], C3[4], C4[4], A5[4], B5c[4], C6[4], C7[8];
    float WIi[4], WIg[4], WIo[4], W3r[16], W4r[8], W5r[8];
#pragma unroll
    for (int j = 0; j < 4; ++j) {
        M1[j] = cv1w[l * 32 + 28 + j];
        M2[j] = cv2w[l * 32 + 28 + j];
        C3[j] = cv3w[l * 4 + j];
        C4[j] = cv4w[l * 4 + j];
        A5[j] = cv5w[l * 16 + j];
        B5c[j] = cv5w[l * 16 + 4 + j] + cv5w[l * 16 + 8 + j] + cv5w[l * 16 + 12 + j];
        C6[j] = cv6w[l * 4 + j];
        WIi[j] = Wih[l * 8 + j];
        WIg[j] = Wih[(8 + l) * 8 + j];
        WIo[j] = Wih[(12 + l) * 8 + j];
    }
#pragma unroll
    for (int j = 0; j < 8; ++j) {
        C7[j]  = cv7w[l * 8 + j];
        W4r[j] = W4[l * 8 + j];
        W5r[j] = W5[l * 8 + j];
    }
#pragma unroll
    for (int j = 0; j < 16; ++j) W3r[j] = W3[l * 16 + j];
    const float C3b = cv3b[l], C4b = cv4b[l], C5b = cv5b[l], C6b = cv6b[l], C7b = cv7b[l];
    const float BIi = bih[l] + bhh[l];
    const float BIg = bih[8 + l] + bhh[8 + l];
    const float BIo = bih[12 + l] + bhh[12 + l];
    const float B3b = b3[l], B4b = b4[l], B5b = b5[l];
    const float SC = 0.70710678118654752f;  // 1/sqrt(2)

    float P[NS], c1c[NS], c2c[NS];
#pragma unroll
    for (int s = 0; s < NS; ++s) {
        P[s] = 0.f;
        c1c[s] = g_c12[start[s] * 8 + l];
        c2c[s] = g_c12[start[s] * 8 + 4 + l];
    }

    const int NSTEP = WARMUP + CHUNK;
    for (int i = 0; i < NSTEP; ++i) {
#pragma unroll
        for (int s = 0; s < NS; ++s) {
            const int t  = start[s] + i;
            const int tn = t + 1;
            float c1n = g_c12[tn * 8 + l];
            float c2n = g_c12[tn * 8 + 4 + l];

            // gather P across the group
            float p0 = SHFL4(P[s], 0), p1 = SHFL4(P[s], 1), p2 = SHFL4(P[s], 2), p3 = SHFL4(P[s], 3);

            // x1 = silu(cv1@u), y2 = silu(cv2@u)   (x_t part folded into c1/c2)
            float x1 = fsilu(dot4(M1, p0, p1, p2, p3, c1c[s]));
            float y2 = fsilu(dot4(M2, p0, p1, p2, p3, c2c[s]));

            // x3 = silu(cv3 @ x1)
            float a0 = SHFL4(x1, 0), a1 = SHFL4(x1, 1), a2 = SHFL4(x1, 2), a3 = SHFL4(x1, 3);
            float x3 = fsilu(dot4(C3, a0, a1, a2, a3, C3b));

            // x4 = silu(cv4 @ x3)
            float d0 = SHFL4(x3, 0), d1 = SHFL4(x3, 1), d2 = SHFL4(x3, 2), d3 = SHFL4(x3, 3);
            float x4 = fsilu(dot4(C4, d0, d1, d2, d3, C4b));

            // t5 = silu(A5 @ x4 + B5 @ relu(x4) + cv5_b)     (SPP concat folded)
            float e0 = SHFL4(x4, 0), e1 = SHFL4(x4, 1), e2 = SHFL4(x4, 2), e3 = SHFL4(x4, 3);
            float r0 = fmaxf(e0, 0.f), r1 = fmaxf(e1, 0.f), r2 = fmaxf(e2, 0.f), r3 = fmaxf(e3, 0.f);
            float sa = fmaf(A5[0], e0, C5b); sa = fmaf(A5[1], e1, sa);
            float sb = A5[2] * e2;           sb = fmaf(A5[3], e3, sb);
            float sc = B5c[0] * r0;          sc = fmaf(B5c[1], r1, sc);
            float sd = B5c[2] * r2;          sd = fmaf(B5c[3], r3, sd);
            float t5 = fsilu((sa + sb) + (sc + sd));

            // y1 = silu(cv6 @ t5)
            float f0 = SHFL4(t5, 0), f1 = SHFL4(t5, 1), f2 = SHFL4(t5, 2), f3 = SHFL4(t5, 3);
            float y1 = fsilu(dot4(C6, f0, f1, f2, f3, C6b));

            // P1 = silu(cv7 @ [y1; y2])
            float g0 = SHFL4(y1, 0), g1 = SHFL4(y1, 1), g2 = SHFL4(y1, 2), g3 = SHFL4(y1, 3);
            float h0 = SHFL4(y2, 0), h1 = SHFL4(y2, 1), h2 = SHFL4(y2, 2), h3 = SHFL4(y2, 3);
            float pa = fmaf(C7[0], g0, C7b); pa = fmaf(C7[1], g1, pa);
            float pb = C7[2] * g2;           pb = fmaf(C7[3], g3, pb);
            float pc = C7[4] * h0;           pc = fmaf(C7[5], h1, pc);
            float pd = C7[6] * h2;           pd = fmaf(C7[7], h3, pd);
            float P1 = fsilu((pa + pb) + (pc + pd));

            float q0 = SHFL4(P1, 0), q1 = SHFL4(P1, 1), q2 = SHFL4(P1, 2), q3 = SHFL4(P1, 3);

            // LSTM single step from zero state (forget gate dead: f*c0 == 0)
            float gi = dot4(WIi, q0, q1, q2, q3, BIi);
            float gg = dot4(WIg, q0, q1, q2, q3, BIg);
            float go = dot4(WIo, q0, q1, q2, q3, BIo);
            float cc = fsigm(gi) * ftanhf_(gg);
            float S0 = fsigm(go) * ftanhf_(cc);

            // chan_att(S0, 2): 2x2 row softmax -> sigmoid of diff
            float s0 = SHFL4(S0, 0), s1 = SHFL4(S0, 1), s2 = SHFL4(S0, 2), s3 = SHFL4(S0, 3);
            float d00 = fmaf(s0, s0, s1 * s1);
            float d01 = fmaf(s0, s2, s1 * s3);
            float d11 = fmaf(s2, s2, s3 * s3);
            float arg = (l == 0) ? (d00 - d01) : (l == 1) ? (d01 - d00)
                      : (l == 2) ? (d01 - d11) : (d11 - d01);
            float S = fsigm(arg * SC);

            // chan_att([P1; S], 4): rows (q0,q1),(q2,q3),(u0,u1),(u2,u3); lane l owns row l
            float u0 = SHFL4(S, 0), u1 = SHFL4(S, 1), u2 = SHFL4(S, 2), u3 = SHFL4(S, 3);
            float ra = (l == 0) ? q0 : (l == 1) ? q2 : (l == 2) ? u0 : u2;
            float rb = (l == 0) ? q1 : (l == 1) ? q3 : (l == 2) ? u1 : u3;
            float z0 = __expf(SC * fmaf(ra, q0, rb * q1));
            float z1 = __expf(SC * fmaf(ra, q2, rb * q3));
            float z2 = __expf(SC * fmaf(ra, u0, rb * u1));
            float z3 = __expf(SC * fmaf(ra, u2, rb * u3));
            float inv = __fdividef(1.f, ((z0 + z1) + (z2 + z3)));
            float k0 = z0 * inv, k1 = z1 * inv, k2 = z2 * inv, k3 = z3 * inv;

            // Kt = relu(W3 @ K16 + b3) — 4 parallel chains of 4 + tree add
            float ka = B3b, kb = 0.f, kc = 0.f, kd = 0.f;
            {
                float w00 = SHFL4(k0, 0), w01 = SHFL4(k1, 0), w02 = SHFL4(k2, 0), w03 = SHFL4(k3, 0);
                float w10 = SHFL4(k0, 1), w11 = SHFL4(k1, 1), w12 = SHFL4(k2, 1), w13 = SHFL4(k3, 1);
                float w20 = SHFL4(k0, 2), w21 = SHFL4(k1, 2), w22 = SHFL4(k2, 2), w23 = SHFL4(k3, 2);
                float w30 = SHFL4(k0, 3), w31 = SHFL4(k1, 3), w32 = SHFL4(k2, 3), w33 = SHFL4(k3, 3);
                ka = fmaf(W3r[0],  w00, ka); ka = fmaf(W3r[1],  w01, ka);
                ka = fmaf(W3r[2],  w02, ka); ka = fmaf(W3r[3],  w03, ka);
                kb = fmaf(W3r[4],  w10, kb); kb = fmaf(W3r[5],  w11, kb);
                kb = fmaf(W3r[6],  w12, kb); kb = fmaf(W3r[7],  w13, kb);
                kc = fmaf(W3r[8],  w20, kc); kc = fmaf(W3r[9],  w21, kc);
                kc = fmaf(W3r[10], w22, kc); kc = fmaf(W3r[11], w23, kc);
                kd = fmaf(W3r[12], w30, kd); kd = fmaf(W3r[13], w31, kd);
                kd = fmaf(W3r[14], w32, kd); kd = fmaf(W3r[15], w33, kd);
            }
            float kt = fmaxf((ka + kb) + (kc + kd), 0.f);

            // o4 = relu(W4 @ [S; Kt] + b4)
            float m0 = SHFL4(kt, 0), m1 = SHFL4(kt, 1), m2 = SHFL4(kt, 2), m3 = SHFL4(kt, 3);
            float oa = fmaf(W4r[0], u0, B4b); oa = fmaf(W4r[1], u1, oa);
            float ob = W4r[2] * u2;           ob = fmaf(W4r[3], u3, ob);
            float oc = W4r[4] * m0;           oc = fmaf(W4r[5], m1, oc);
            float od = W4r[6] * m2;           od = fmaf(W4r[7], m3, od);
            float o4 = fmaxf((oa + ob) + (oc + od), 0.f);

            // P2 = relu(W5 @ [P1; o4] + b5)
            float n0 = SHFL4(o4, 0), n1 = SHFL4(o4, 1), n2 = SHFL4(o4, 2), n3 = SHFL4(o4, 3);
            float va = fmaf(W5r[0], q0, B5b); va = fmaf(W5r[1], q1, va);
            float vb = W5r[2] * q2;           vb = fmaf(W5r[3], q3, vb);
            float vc = W5r[4] * n0;           vc = fmaf(W5r[5], n1, vc);
            float vd = W5r[6] * n2;           vd = fmaf(W5r[7], n3, vd);
            P[s] = fmaxf((va + vb) + (vc + vd), 0.f);

            if (t >= pay_lo[s] && t < pay_lo[s] + CHUNK) out[t * 4 + l] = kt;

            c1c[s] = c1n;
            c2c[s] = c2n;
        }
    }
}

// ---------------------------------------------------------------------------
extern "C" void kernel_launch(void* const* d_in, const int* in_sizes, int n_in,
                              void* d_out, int out_size) {
    const float* x    = (const float*)d_in[0];
    const float* W1   = (const float*)d_in[1];
    const float* b1   = (const float*)d_in[2];
    const float* cv1w = (const float*)d_in[3];
    const float* cv1b = (const float*)d_in[4];
    const float* cv2w = (const float*)d_in[5];
    const float* cv2b = (const float*)d_in[6];
    const float* cv3w = (const float*)d_in[7];
    const float* cv3b = (const float*)d_in[8];
    const float* cv4w = (const float*)d_in[9];
    const float* cv4b = (const float*)d_in[10];
    const float* cv5w = (const float*)d_in[11];
    const float* cv5b = (const float*)d_in[12];
    const float* cv6w = (const float*)d_in[13];
    const float* cv6b = (const float*)d_in[14];
    const float* cv7w = (const float*)d_in[15];
    const float* cv7b = (const float*)d_in[16];
    const float* Wih  = (const float*)d_in[17];
    const float* bih  = (const float*)d_in[18];
    const float* bhh  = (const float*)d_in[19];
    const float* W3   = (const float*)d_in[20];
    const float* b3   = (const float*)d_in[21];
    const float* W4   = (const float*)d_in[22];
    const float* b4   = (const float*)d_in[23];
    const float* W5   = (const float*)d_in[24];
    const float* b5   = (const float*)d_in[25];
    float* out = (float*)d_out;

    precompute_kernel<<<T_STEPS / 256, 256>>>(x, W1, b1, cv1w, cv1b, cv2w, cv2b);
    scan_kernel<<<NWARPS, 32>>>(cv1w, cv2w, cv3w, cv3b, cv4w, cv4b, cv5w, cv5b,
                                cv6w, cv6b, cv7w, cv7b, Wih, bih, bhh,
                                W3, b3, W4, b4, W5, b5, out);
}

// round 4
// speedup vs baseline: 3.4889x; 3.4889x over previous
#include <cuda_runtime.h>

#define T_STEPS 65536
#define CHUNK   8
#define WARMUP  80
#define NCHUNK  (T_STEPS / CHUNK)          // 8192 chunks
#define GROUPS_PER_WARP 8
#define NWARPS  (NCHUNK / GROUPS_PER_WARP) // 1024 single-warp blocks

// Scratch for precomputed per-step constants: c1[4], c2[4] per t (+1 row pad for prefetch)
__device__ float g_c12[(T_STEPS + 1) * 8];

// MUFU.TANH — single 16-cycle op on sm_75+, max abs err ~1e-5
__device__ __forceinline__ float ftanh(float x) {
    float r; asm("tanh.approx.f32 %0, %1;" : "=f"(r) : "f"(x)); return r;
}
__device__ __forceinline__ float fsigm(float x) { return fmaf(0.5f, ftanh(0.5f * x), 0.5f); }
__device__ __forceinline__ float fsilu(float x) { float h = 0.5f * x; return fmaf(h, ftanh(h), h); }

#define SHFL4(v, r) __shfl_sync(0xffffffffu, (v), (r), 4)

// ---------------------------------------------------------------------------
// Parallel precompute: a_t = relu(W1 x_t + b1);
//   c1_t = cv1_b + cv1_w[:,4:28] @ a_t   (the zeros4 block multiplies cols 0:4)
//   c2_t = cv2_b + cv2_w[:,4:28] @ a_t
// ---------------------------------------------------------------------------
__global__ void precompute_kernel(const float* __restrict__ x,
                                  const float* __restrict__ W1, const float* __restrict__ b1,
                                  const float* __restrict__ cv1w, const float* __restrict__ cv1b,
                                  const float* __restrict__ cv2w, const float* __restrict__ cv2b) {
    int t = blockIdx.x * blockDim.x + threadIdx.x;
    if (t >= T_STEPS) return;
    float x0 = x[2 * t], x1 = x[2 * t + 1];
    float a[24];
#pragma unroll
    for (int j = 0; j < 24; ++j) {
        float v = fmaf(W1[2 * j], x0, fmaf(W1[2 * j + 1], x1, b1[j]));
        a[j] = fmaxf(v, 0.f);
    }
#pragma unroll
    for (int i = 0; i < 4; ++i) {
        float c1 = cv1b[i], c2 = cv2b[i];
#pragma unroll
        for (int j = 0; j < 24; ++j) {
            c1 = fmaf(cv1w[i * 32 + 4 + j], a[j], c1);
            c2 = fmaf(cv2w[i * 32 + 4 + j], a[j], c2);
        }
        g_c12[t * 8 + i]     = c1;
        g_c12[t * 8 + 4 + i] = c2;
    }
}

// 4-term dot with split chains
__device__ __forceinline__ float dot4(const float* w, float v0, float v1, float v2, float v3, float c) {
    float a = fmaf(w[0], v0, c);
    a = fmaf(w[1], v1, a);
    float b = w[2] * v2;
    b = fmaf(w[3], v3, b);
    return a + b;
}

// ---------------------------------------------------------------------------
// Sequential scan: 4 lanes cooperate per chunk (lane l owns row l of every
// 4-row matrix), 8 chunks per warp; short warmup-from-zero (contraction
// g <= 0.87 measured) makes chunks independent.
// ---------------------------------------------------------------------------
__global__ void __launch_bounds__(32, 1)
scan_kernel(const float* __restrict__ cv1w, const float* __restrict__ cv2w,
            const float* __restrict__ cv3w, const float* __restrict__ cv3b,
            const float* __restrict__ cv4w, const float* __restrict__ cv4b,
            const float* __restrict__ cv5w, const float* __restrict__ cv5b,
            const float* __restrict__ cv6w, const float* __restrict__ cv6b,
            const float* __restrict__ cv7w, const float* __restrict__ cv7b,
            const float* __restrict__ Wih,  const float* __restrict__ bih,
            const float* __restrict__ bhh,
            const float* __restrict__ W3,   const float* __restrict__ b3,
            const float* __restrict__ W4,   const float* __restrict__ b4,
            const float* __restrict__ W5,   const float* __restrict__ b5,
            float* __restrict__ out) {
    const int l   = threadIdx.x & 3;                       // lane within group
    const int grp = (blockIdx.x * 32 + threadIdx.x) >> 2;  // global chunk id
    const int pay_lo = grp * CHUNK;
    const int pay_hi = pay_lo + CHUNK;
    int start = pay_lo - WARMUP;
    if (start < 0) start = 0;   // early chunks: exact from t=0 (true init P=0)

    // ---- per-lane weight rows (registers) ----
    float M1[4], M2[4], C3[4], C4[4], A5[4], B5c[4], C6[4], C7[8];
    float WIi[4], WIg[4], WIo[4], W3r[16], W4r[8], W5r[8];
#pragma unroll
    for (int j = 0; j < 4; ++j) {
        M1[j] = cv1w[l * 32 + 28 + j];
        M2[j] = cv2w[l * 32 + 28 + j];
        C3[j] = cv3w[l * 4 + j];
        C4[j] = cv4w[l * 4 + j];
        A5[j] = cv5w[l * 16 + j];
        B5c[j] = cv5w[l * 16 + 4 + j] + cv5w[l * 16 + 8 + j] + cv5w[l * 16 + 12 + j];
        C6[j] = cv6w[l * 4 + j];
        WIi[j] = Wih[l * 8 + j];
        WIg[j] = Wih[(8 + l) * 8 + j];
        WIo[j] = Wih[(12 + l) * 8 + j];
    }
#pragma unroll
    for (int j = 0; j < 8; ++j) {
        C7[j]  = cv7w[l * 8 + j];
        W4r[j] = W4[l * 8 + j];
        W5r[j] = W5[l * 8 + j];
    }
#pragma unroll
    for (int j = 0; j < 16; ++j) W3r[j] = W3[l * 16 + j];
    const float C3b = cv3b[l], C4b = cv4b[l], C5b = cv5b[l], C6b = cv6b[l], C7b = cv7b[l];
    const float BIi = bih[l] + bhh[l];
    const float BIg = bih[8 + l] + bhh[8 + l];
    const float BIo = bih[12 + l] + bhh[12 + l];
    const float B3b = b3[l], B4b = b4[l], B5b = b5[l];
    const float SC = 0.70710678118654752f;  // 1/sqrt(2)

    float P = 0.f;
    float c1c = g_c12[start * 8 + l];
    float c2c = g_c12[start * 8 + 4 + l];

    const int NSTEP = WARMUP + CHUNK;
    for (int i = 0; i < NSTEP; ++i) {
        const int t  = start + i;
        const int tn = t + 1;
        float c1n = g_c12[tn * 8 + l];
        float c2n = g_c12[tn * 8 + 4 + l];

        // gather P across the group
        float p0 = SHFL4(P, 0), p1 = SHFL4(P, 1), p2 = SHFL4(P, 2), p3 = SHFL4(P, 3);

        // x1 = silu(cv1@u), y2 = silu(cv2@u)   (x_t part folded into c1/c2)
        float x1 = fsilu(dot4(M1, p0, p1, p2, p3, c1c));
        float y2 = fsilu(dot4(M2, p0, p1, p2, p3, c2c));

        // x3 = silu(cv3 @ x1)
        float a0 = SHFL4(x1, 0), a1 = SHFL4(x1, 1), a2 = SHFL4(x1, 2), a3 = SHFL4(x1, 3);
        float x3 = fsilu(dot4(C3, a0, a1, a2, a3, C3b));

        // x4 = silu(cv4 @ x3)
        float d0 = SHFL4(x3, 0), d1 = SHFL4(x3, 1), d2 = SHFL4(x3, 2), d3 = SHFL4(x3, 3);
        float x4 = fsilu(dot4(C4, d0, d1, d2, d3, C4b));

        // t5 = silu(A5 @ x4 + B5 @ relu(x4) + cv5_b)     (SPP concat folded)
        float e0 = SHFL4(x4, 0), e1 = SHFL4(x4, 1), e2 = SHFL4(x4, 2), e3 = SHFL4(x4, 3);
        float r0 = fmaxf(e0, 0.f), r1 = fmaxf(e1, 0.f), r2 = fmaxf(e2, 0.f), r3 = fmaxf(e3, 0.f);
        float sa = fmaf(A5[0], e0, C5b); sa = fmaf(A5[1], e1, sa);
        float sb = A5[2] * e2;           sb = fmaf(A5[3], e3, sb);
        float sc = B5c[0] * r0;          sc = fmaf(B5c[1], r1, sc);
        float sd = B5c[2] * r2;          sd = fmaf(B5c[3], r3, sd);
        float t5 = fsilu((sa + sb) + (sc + sd));

        // y1 = silu(cv6 @ t5)
        float f0 = SHFL4(t5, 0), f1 = SHFL4(t5, 1), f2 = SHFL4(t5, 2), f3 = SHFL4(t5, 3);
        float y1 = fsilu(dot4(C6, f0, f1, f2, f3, C6b));

        // P1 = silu(cv7 @ [y1; y2])
        float g0 = SHFL4(y1, 0), g1 = SHFL4(y1, 1), g2 = SHFL4(y1, 2), g3 = SHFL4(y1, 3);
        float h0 = SHFL4(y2, 0), h1 = SHFL4(y2, 1), h2 = SHFL4(y2, 2), h3 = SHFL4(y2, 3);
        float pa = fmaf(C7[0], g0, C7b); pa = fmaf(C7[1], g1, pa);
        float pb = C7[2] * g2;           pb = fmaf(C7[3], g3, pb);
        float pc = C7[4] * h0;           pc = fmaf(C7[5], h1, pc);
        float pd = C7[6] * h2;           pd = fmaf(C7[7], h3, pd);
        float P1 = fsilu((pa + pb) + (pc + pd));

        float q0 = SHFL4(P1, 0), q1 = SHFL4(P1, 1), q2 = SHFL4(P1, 2), q3 = SHFL4(P1, 3);

        // LSTM single step from zero state (forget gate dead: f*c0 == 0)
        float gi = dot4(WIi, q0, q1, q2, q3, BIi);
        float gg = dot4(WIg, q0, q1, q2, q3, BIg);
        float go = dot4(WIo, q0, q1, q2, q3, BIo);
        float cc = fsigm(gi) * ftanh(gg);
        float S0 = fsigm(go) * ftanh(cc);

        // chan_att(S0, 2): 2x2 row softmax -> sigmoid of diff
        float s0 = SHFL4(S0, 0), s1 = SHFL4(S0, 1), s2 = SHFL4(S0, 2), s3 = SHFL4(S0, 3);
        float d00 = fmaf(s0, s0, s1 * s1);
        float d01 = fmaf(s0, s2, s1 * s3);
        float d11 = fmaf(s2, s2, s3 * s3);
        float arg = (l == 0) ? (d00 - d01) : (l == 1) ? (d01 - d00)
                  : (l == 2) ? (d01 - d11) : (d11 - d01);
        float S = fsigm(arg * SC);

        // chan_att([P1; S], 4): rows (q0,q1),(q2,q3),(u0,u1),(u2,u3); lane l owns row l
        float u0 = SHFL4(S, 0), u1 = SHFL4(S, 1), u2 = SHFL4(S, 2), u3 = SHFL4(S, 3);
        float ra = (l == 0) ? q0 : (l == 1) ? q2 : (l == 2) ? u0 : u2;
        float rb = (l == 0) ? q1 : (l == 1) ? q3 : (l == 2) ? u1 : u3;
        float z0 = __expf(SC * fmaf(ra, q0, rb * q1));
        float z1 = __expf(SC * fmaf(ra, q2, rb * q3));
        float z2 = __expf(SC * fmaf(ra, u0, rb * u1));
        float z3 = __expf(SC * fmaf(ra, u2, rb * u3));
        float inv = __fdividef(1.f, ((z0 + z1) + (z2 + z3)));
        float k0 = z0 * inv, k1 = z1 * inv, k2 = z2 * inv, k3 = z3 * inv;

        // Kt = relu(W3 @ K16 + b3) — 4 parallel chains of 4 + tree add
        float ka = B3b, kb = 0.f, kc = 0.f, kd = 0.f;
        {
            float w00 = SHFL4(k0, 0), w01 = SHFL4(k1, 0), w02 = SHFL4(k2, 0), w03 = SHFL4(k3, 0);
            float w10 = SHFL4(k0, 1), w11 = SHFL4(k1, 1), w12 = SHFL4(k2, 1), w13 = SHFL4(k3, 1);
            float w20 = SHFL4(k0, 2), w21 = SHFL4(k1, 2), w22 = SHFL4(k2, 2), w23 = SHFL4(k3, 2);
            float w30 = SHFL4(k0, 3), w31 = SHFL4(k1, 3), w32 = SHFL4(k2, 3), w33 = SHFL4(k3, 3);
            ka = fmaf(W3r[0],  w00, ka); ka = fmaf(W3r[1],  w01, ka);
            ka = fmaf(W3r[2],  w02, ka); ka = fmaf(W3r[3],  w03, ka);
            kb = fmaf(W3r[4],  w10, kb); kb = fmaf(W3r[5],  w11, kb);
            kb = fmaf(W3r[6],  w12, kb); kb = fmaf(W3r[7],  w13, kb);
            kc = fmaf(W3r[8],  w20, kc); kc = fmaf(W3r[9],  w21, kc);
            kc = fmaf(W3r[10], w22, kc); kc = fmaf(W3r[11], w23, kc);
            kd = fmaf(W3r[12], w30, kd); kd = fmaf(W3r[13], w31, kd);
            kd = fmaf(W3r[14], w32, kd); kd = fmaf(W3r[15], w33, kd);
        }
        float kt = fmaxf((ka + kb) + (kc + kd), 0.f);

        // o4 = relu(W4 @ [S; Kt] + b4)
        float m0 = SHFL4(kt, 0), m1 = SHFL4(kt, 1), m2 = SHFL4(kt, 2), m3 = SHFL4(kt, 3);
        float oa = fmaf(W4r[0], u0, B4b); oa = fmaf(W4r[1], u1, oa);
        float ob = W4r[2] * u2;           ob = fmaf(W4r[3], u3, ob);
        float oc = W4r[4] * m0;           oc = fmaf(W4r[5], m1, oc);
        float od = W4r[6] * m2;           od = fmaf(W4r[7], m3, od);
        float o4 = fmaxf((oa + ob) + (oc + od), 0.f);

        // P2 = relu(W5 @ [P1; o4] + b5)
        float n0 = SHFL4(o4, 0), n1 = SHFL4(o4, 1), n2 = SHFL4(o4, 2), n3 = SHFL4(o4, 3);
        float va = fmaf(W5r[0], q0, B5b); va = fmaf(W5r[1], q1, va);
        float vb = W5r[2] * q2;           vb = fmaf(W5r[3], q3, vb);
        float vc = W5r[4] * n0;           vc = fmaf(W5r[5], n1, vc);
        float vd = W5r[6] * n2;           vd = fmaf(W5r[7], n3, vd);
        P = fmaxf((va + vb) + (vc + vd), 0.f);

        if (t >= pay_lo && t < pay_hi) out[t * 4 + l] = kt;

        c1c = c1n;
        c2c = c2n;
    }
}

// ---------------------------------------------------------------------------
extern "C" void kernel_launch(void* const* d_in, const int* in_sizes, int n_in,
                              void* d_out, int out_size) {
    const float* x    = (const float*)d_in[0];
    const float* W1   = (const float*)d_in[1];
    const float* b1   = (const float*)d_in[2];
    const float* cv1w = (const float*)d_in[3];
    const float* cv1b = (const float*)d_in[4];
    const float* cv2w = (const float*)d_in[5];
    const float* cv2b = (const float*)d_in[6];
    const float* cv3w = (const float*)d_in[7];
    const float* cv3b = (const float*)d_in[8];
    const float* cv4w = (const float*)d_in[9];
    const float* cv4b = (const float*)d_in[10];
    const float* cv5w = (const float*)d_in[11];
    const float* cv5b = (const float*)d_in[12];
    const float* cv6w = (const float*)d_in[13];
    const float* cv6b = (const float*)d_in[14];
    const float* cv7w = (const float*)d_in[15];
    const float* cv7b = (const float*)d_in[16];
    const float* Wih  = (const float*)d_in[17];
    const float* bih  = (const float*)d_in[18];
    const float* bhh  = (const float*)d_in[19];
    const float* W3   = (const float*)d_in[20];
    const float* b3   = (const float*)d_in[21];
    const float* W4   = (const float*)d_in[22];
    const float* b4   = (const float*)d_in[23];
    const float* W5   = (const float*)d_in[24];
    const float* b5   = (const float*)d_in[25];
    float* out = (float*)d_out;

    precompute_kernel<<<T_STEPS / 256, 256>>>(x, W1, b1, cv1w, cv1b, cv2w, cv2b);
    scan_kernel<<<NWARPS, 32>>>(cv1w, cv2w, cv3w, cv3b, cv4w, cv4b, cv5w, cv5b,
                                cv6w, cv6b, cv7w, cv7b, Wih, bih, bhh,
                                W3, b3, W4, b4, W5, b5, out);
}